// round 3
// baseline (speedup 1.0000x reference)
#include <cuda_runtime.h>
#include <math.h>

#define HIDDEN 64
#define BATCH  16
#define TSTEPS 16
#define NNPOS  4096
#define OC     256
#define TILE_N 64     // positions per block
#define CH     4      // ic chunk staged in smem
#define HPW    58     // packed-h entries per ic: i in [0,57]

typedef unsigned long long u64;

// ---- persistent scratch (device globals; no allocation allowed) ----
__device__ float g_h0[BATCH * HIDDEN * NNPOS];
__device__ float g_h1[BATCH * HIDDEN * NNPOS];
__device__ float g_c [BATCH * HIDDEN * NNPOS];
__device__ float g_w [3 * 65 * OC];   // [kh][ic][oc]; ic 0..63 = h-channels, ic 64 = x

// ---- packed fp32x2 helpers (FFMA2 path; ptxas never emits these from C++) ----
__device__ __forceinline__ u64 pk2(float lo, float hi) {
    u64 r; asm("mov.b64 %0,{%1,%2};" : "=l"(r) : "f"(lo), "f"(hi)); return r;
}
__device__ __forceinline__ u64 dup2(float v) { return pk2(v, v); }
__device__ __forceinline__ void unpk(u64 v, float& a, float& b) {
    asm("mov.b64 {%0,%1},%2;" : "=f"(a), "=f"(b) : "l"(v));
}
__device__ __forceinline__ void ffma2(u64& d, u64 a, u64 b) {
    asm("fma.rn.f32x2 %0,%1,%2,%0;" : "+l"(d) : "l"(a), "l"(b));
}

// Repack conv_w (OIHW, [256,65,3,3], only kw=1 matters) -> g_w[kh][ic][oc]
__global__ void repack_w(const float* __restrict__ conv_w) {
    int idx = blockIdx.x * blockDim.x + threadIdx.x;
    if (idx >= 3 * 65 * OC) return;
    int oc = idx & (OC - 1);
    int ic = (idx >> 8) % 65;
    int kh = idx / (65 * OC);
    int src_ic = (ic < 64) ? (ic + 1) : 0;   // input channel 0 of conv is x
    g_w[idx] = conv_w[((oc * 65 + src_ic) * 3 + kh) * 3 + 1];
}

__global__ void zero_state() {
    size_t i = (size_t)blockIdx.x * blockDim.x + threadIdx.x;
    size_t stride = (size_t)gridDim.x * blockDim.x;
    const size_t total = (size_t)BATCH * HIDDEN * NNPOS;
    for (; i < total; i += stride) { g_h0[i] = 0.f; g_c[i] = 0.f; }
}

__device__ __forceinline__ float fast_sigmoid(float x) {
    return 1.f / (1.f + __expf(-x));
}
__device__ __forceinline__ float fast_tanh(float x) {
    float e = __expf(-2.f * x);
    return (1.f - e) / (1.f + e);
}

__global__ void __launch_bounds__(256, 2)
lstm_step(const float* __restrict__ x, const float* __restrict__ conv_b,
          int t, int parity) {
    const float* __restrict__ hin  = parity ? g_h1 : g_h0;
    float*       __restrict__ hout = parity ? g_h0 : g_h1;

    const int b   = blockIdx.y;
    const int n0  = blockIdx.x * TILE_N;
    const int tid = threadIdx.x;
    const int ch  = tid & 63;      // hidden channel
    const int q   = tid >> 6;      // position quadrant (16 positions each)

    // hp_s[ic][i] = ( h[n0-1+i], h[n0+7+i] )  -> packed pair 8 positions apart
    __shared__ u64   hp_s[HIDDEN][HPW];
    __shared__ u64   xp_s[HPW];
    __shared__ float w_s[3][CH][OC];

    const float* hb = hin + (size_t)b * HIDDEN * NNPOS;
    for (int m = tid; m < HIDDEN * HPW; m += 256) {
        int ic = m / HPW;
        int i  = m % HPW;
        int nlo = n0 - 1 + i;
        int nhi = n0 + 7 + i;
        float lo = (nlo >= 0 && nlo < NNPOS) ? hb[(size_t)ic * NNPOS + nlo] : 0.f;
        float hi = (nhi < NNPOS)             ? hb[(size_t)ic * NNPOS + nhi] : 0.f;
        hp_s[ic][i] = pk2(lo, hi);
    }
    if (tid < HPW) {
        const float* xb = x + ((size_t)b * TSTEPS + t) * NNPOS;
        int nlo = n0 - 1 + tid;
        int nhi = n0 + 7 + tid;
        float lo = (nlo >= 0 && nlo < NNPOS) ? xb[nlo] : 0.f;
        float hi = (nhi < NNPOS)             ? xb[nhi] : 0.f;
        xp_s[tid] = pk2(lo, hi);
    }

    // accumulators: 4 gates x 8 packed position-pairs (16 positions)
    u64 acc[4][8];
    #pragma unroll
    for (int g = 0; g < 4; g++) {
        u64 bv = dup2(conv_b[g * 64 + ch]);
        #pragma unroll
        for (int j = 0; j < 8; j++) acc[g][j] = bv;
    }

    __syncthreads();   // hp_s / xp_s ready

    // x-channel contribution (ic index 64 in g_w); weights via global (L1-cached)
    {
        u64 xr[10];
        #pragma unroll
        for (int i = 0; i < 10; i++) xr[i] = xp_s[q * 16 + i];
        #pragma unroll
        for (int g = 0; g < 4; g++) {
            u64 w0 = dup2(g_w[(0 * 65 + 64) * OC + g * 64 + ch]);
            u64 w1 = dup2(g_w[(1 * 65 + 64) * OC + g * 64 + ch]);
            u64 w2 = dup2(g_w[(2 * 65 + 64) * OC + g * 64 + ch]);
            #pragma unroll
            for (int j = 0; j < 8; j++) {
                ffma2(acc[g][j], w0, xr[j]);
                ffma2(acc[g][j], w1, xr[j + 1]);
                ffma2(acc[g][j], w2, xr[j + 2]);
            }
        }
    }

    // h-channel contributions, weights staged in SMEM chunks of CH ics
    #pragma unroll 1
    for (int c0 = 0; c0 < 64; c0 += CH) {
        __syncthreads();
        #pragma unroll
        for (int m = tid; m < 3 * CH * OC; m += 256) {
            int oc = m & (OC - 1);
            int r  = m >> 8;        // 0..11
            int ii = r % CH;
            int kh = r / CH;
            w_s[kh][ii][oc] = g_w[(kh * 65 + (c0 + ii)) * OC + oc];
        }
        __syncthreads();

        #pragma unroll
        for (int ii = 0; ii < CH; ii++) {
            const int ic = c0 + ii;
            u64 hr[10];
            #pragma unroll
            for (int i = 0; i < 10; i++) hr[i] = hp_s[ic][q * 16 + i];
            #pragma unroll
            for (int g = 0; g < 4; g++) {
                u64 w0 = dup2(w_s[0][ii][g * 64 + ch]);
                u64 w1 = dup2(w_s[1][ii][g * 64 + ch]);
                u64 w2 = dup2(w_s[2][ii][g * 64 + ch]);
                #pragma unroll
                for (int j = 0; j < 8; j++) {
                    ffma2(acc[g][j], w0, hr[j]);
                    ffma2(acc[g][j], w1, hr[j + 1]);
                    ffma2(acc[g][j], w2, hr[j + 2]);
                }
            }
        }
    }

    // LSTM elementwise; lanes map to positions (p, p+8); c updated in place
    size_t base = (size_t)b * HIDDEN * NNPOS + (size_t)ch * NNPOS + n0 + q * 16;
    #pragma unroll
    for (int j = 0; j < 8; j++) {
        float i0, i1, f0, f1, o0, o1, g0, g1;
        unpk(acc[0][j], i0, i1);
        unpk(acc[1][j], f0, f1);
        unpk(acc[2][j], o0, o1);
        unpk(acc[3][j], g0, g1);
        {
            float ig = fast_sigmoid(i0), fg = fast_sigmoid(f0), og = fast_sigmoid(o0);
            float gg = fast_tanh(g0);
            float c2 = fg * g_c[base + j] + ig * gg;
            g_c[base + j]  = c2;
            hout[base + j] = og * fast_tanh(c2);
        }
        {
            float ig = fast_sigmoid(i1), fg = fast_sigmoid(f1), og = fast_sigmoid(o1);
            float gg = fast_tanh(g1);
            float c2 = fg * g_c[base + j + 8] + ig * gg;
            g_c[base + j + 8]  = c2;
            hout[base + j + 8] = og * fast_tanh(c2);
        }
    }
}

// Final 1x1 conv over hidden dim + broadcast over TS
__global__ void __launch_bounds__(256)
fc_kernel(const float* __restrict__ fc_w, const float* __restrict__ fc_b,
          float* __restrict__ out) {
    __shared__ float w_s[HIDDEN];
    int tid = threadIdx.x;
    if (tid < HIDDEN) w_s[tid] = fc_w[tid];
    __syncthreads();

    int b = blockIdx.y;
    int n = blockIdx.x * 256 + tid;
    const float* hb = g_h0 + (size_t)b * HIDDEN * NNPOS + n;  // final h lives in g_h0
    float acc = fc_b[0];
    #pragma unroll
    for (int ch = 0; ch < HIDDEN; ch++)
        acc += hb[(size_t)ch * NNPOS] * w_s[ch];

    #pragma unroll
    for (int t = 0; t < TSTEPS; t++)
        out[((size_t)b * TSTEPS + t) * NNPOS + n] = acc;
}

extern "C" void kernel_launch(void* const* d_in, const int* in_sizes, int n_in,
                              void* d_out, int out_size) {
    const float* x      = (const float*)d_in[0];  // [16,16,4096,1]
    const float* conv_w = (const float*)d_in[1];  // [256,65,3,3]
    const float* conv_b = (const float*)d_in[2];  // [256]
    const float* fc_w   = (const float*)d_in[3];  // [1,64,1,1]
    const float* fc_b   = (const float*)d_in[4];  // [1]
    float* out = (float*)d_out;                   // [16,16,4096,1]

    repack_w<<<(3 * 65 * OC + 255) / 256, 256>>>(conv_w);
    zero_state<<<1024, 256>>>();

    dim3 grid(NNPOS / TILE_N, BATCH);
    for (int t = 0; t < TSTEPS; t++)
        lstm_step<<<grid, 256>>>(x, conv_b, t, t & 1);

    fc_kernel<<<dim3(NNPOS / 256, BATCH), 256>>>(fc_w, fc_b, out);
}

// round 7
// speedup vs baseline: 1.9485x; 1.9485x over previous
#include <cuda_runtime.h>
#include <cuda_bf16.h>
#include <math.h>

#define HIDDEN 64
#define BATCH  16
#define TSTEPS 16
#define NNPOS  4096
#define TILE_P 256

typedef unsigned int u32;

// ---- smem layout (bytes) ----
#define A_STRIDE 144            // 64 bf16 = 128B padded to 144 (conflict-free frags)
#define B_STRIDE 400            // 192 bf16 = 384B padded to 400
#define APLANE   (258 * A_STRIDE)          // 37152
#define BPLANE   (128 * B_STRIDE)          // 51200
#define OFF_A    0                          // 2 planes: hi, lo
#define OFF_B    (2 * APLANE)               // 74304; 2 planes
#define OFF_X    (OFF_B + 2 * BPLANE)       // 176704; 258 floats
#define OFF_WX   (OFF_X + 258 * 4)          // 177736; 128*3 floats
#define OFF_BIAS (OFF_WX + 128 * 3 * 4)     // 179272; 128 floats
#define SMEM_BYTES (OFF_BIAS + 512)         // 179784

// ---- persistent scratch ----
// weight image: [hs][plane][n][192] bf16, n-row: gate=(n>>3)&3, chl=(n>>5)*8+(n&7)
__device__ __align__(16) __nv_bfloat16 g_wimg[2 * 2 * 128 * 192];
__device__ __align__(16) __nv_bfloat16 g_hp[2][2][(size_t)BATCH * NNPOS * HIDDEN]; // [buf][plane][(b*NN+p)*64+ch]
__device__ __align__(16) float         g_c[(size_t)BATCH * NNPOS * HIDDEN];

__device__ __forceinline__ float sigm(float v)  { return 1.f / (1.f + __expf(-v)); }
__device__ __forceinline__ float tanhq(float v) { return 1.f - 2.f / (__expf(2.f * v) + 1.f); }

__device__ __forceinline__ void mma16816(float* c, const u32* a, const u32* bf) {
    asm volatile(
        "mma.sync.aligned.m16n8k16.row.col.f32.bf16.bf16.f32 "
        "{%0,%1,%2,%3},{%4,%5,%6,%7},{%8,%9},{%0,%1,%2,%3};"
        : "+f"(c[0]), "+f"(c[1]), "+f"(c[2]), "+f"(c[3])
        : "r"(a[0]), "r"(a[1]), "r"(a[2]), "r"(a[3]), "r"(bf[0]), "r"(bf[1]));
}

// ---- setup: weight image ----
__global__ void repack_img(const float* __restrict__ conv_w) {
    int idx = blockIdx.x * blockDim.x + threadIdx.x;
    if (idx >= 2 * 128 * 192) return;
    int hs  = idx / 24576;
    int rem = idx % 24576;
    int n = rem / 192, k = rem % 192;
    int gate = (n >> 3) & 3;
    int chl  = (n >> 5) * 8 + (n & 7);
    int oc = gate * 64 + hs * 32 + chl;
    int kh = k / 64, ic = k % 64;
    float w = conv_w[((oc * 65 + (ic + 1)) * 3 + kh) * 3 + 1];
    __nv_bfloat16 whi = __float2bfloat16(w);
    __nv_bfloat16 wlo = __float2bfloat16(w - __bfloat162float(whi));
    g_wimg[((size_t)(hs * 2 + 0) * 128 + n) * 192 + k] = whi;
    g_wimg[((size_t)(hs * 2 + 1) * 128 + n) * 192 + k] = wlo;
}

__global__ void zero_state() {
    size_t i = (size_t)blockIdx.x * blockDim.x + threadIdx.x;
    size_t stride = (size_t)gridDim.x * blockDim.x;
    const size_t nc = (size_t)BATCH * NNPOS * HIDDEN;
    for (size_t j = i; j < nc; j += stride) g_c[j] = 0.f;
    u32* h0 = (u32*)&g_hp[0][0][0];            // both planes of buf0 contiguous
    for (size_t j = i; j < nc; j += stride) h0[j] = 0u;
}

// ---- one timestep ----
__global__ void __launch_bounds__(256, 1)
lstm_step(const float* __restrict__ x, const float* __restrict__ conv_w,
          const float* __restrict__ conv_b, int t) {
    extern __shared__ unsigned char sm[];
    const int tid = threadIdx.x, wid = tid >> 5, lane = tid & 31;
    const int g = lane >> 2, tq = lane & 3;
    const int p0 = blockIdx.x * TILE_P;
    const int hs = blockIdx.y;
    const int b  = blockIdx.z;
    const int rd = t & 1, wr = rd ^ 1;

    // ---- stage B: 2 planes x 128 rows x 24 uint4 (FIXED: full 384B rows) ----
    {
        const uint4* src = (const uint4*)(g_wimg + (size_t)hs * 2 * 128 * 192);
        #pragma unroll
        for (int m = tid; m < 2 * 128 * 24; m += 256) {
            int pl = m / 3072, r = (m % 3072) / 24, c = m % 24;
            *(uint4*)(sm + OFF_B + pl * BPLANE + r * B_STRIDE + c * 16) = src[m];
        }
    }
    // ---- stage A (h rows p0-1..p0+256): 2 planes x 258 rows x 8 uint4 ----
    {
        const uint4 z4 = make_uint4(0, 0, 0, 0);
        #pragma unroll
        for (int m = tid; m < 2 * 258 * 8; m += 256) {
            int pl = m / 2064, r = (m % 2064) / 8, c = m % 8;
            int pos = p0 - 1 + r;
            uint4 v = z4;
            if (pos >= 0 && pos < NNPOS)
                v = ((const uint4*)&g_hp[rd][pl][((size_t)b * NNPOS + pos) * 64])[c];
            *(uint4*)(sm + OFF_A + pl * APLANE + r * A_STRIDE + c * 16) = v;
        }
    }
    // ---- stage x, wx, bias ----
    for (int m = tid; m < 258; m += 256) {
        int pos = p0 - 1 + m;
        ((float*)(sm + OFF_X))[m] =
            (pos >= 0 && pos < NNPOS) ? x[((size_t)b * TSTEPS + t) * NNPOS + pos] : 0.f;
    }
    if (tid < 128) {
        int n = tid;
        int gate = (n >> 3) & 3;
        int chl  = (n >> 5) * 8 + (n & 7);
        int oc = gate * 64 + hs * 32 + chl;
        ((float*)(sm + OFF_BIAS))[n] = conv_b[oc];
        #pragma unroll
        for (int kh = 0; kh < 3; kh++)
            ((float*)(sm + OFF_WX))[n * 3 + kh] = conv_w[((oc * 65 + 0) * 3 + kh) * 3 + 1];
    }
    __syncthreads();

    // ---- mainloop: warp tile 64x64, 3 passes (hi*hi, lo*hi, hi*lo) ----
    const int wm = wid >> 1, wn = wid & 1;
    float C[4][8][4];
    #pragma unroll
    for (int mt = 0; mt < 4; mt++)
        #pragma unroll
        for (int nt = 0; nt < 8; nt++)
            #pragma unroll
            for (int r = 0; r < 4; r++) C[mt][nt][r] = 0.f;

    const unsigned char* Arow = sm + OFF_A + (wm * 64 + g) * A_STRIDE + tq * 4;
    const unsigned char* Brow = sm + OFF_B + (wn * 64 + g) * B_STRIDE + tq * 4;

    #pragma unroll 1
    for (int pass = 0; pass < 3; pass++) {
        const unsigned char* Ab = Arow + (pass == 1 ? APLANE : 0);
        const unsigned char* Bb = Brow + (pass == 2 ? BPLANE : 0);
        #pragma unroll 1
        for (int kh = 0; kh < 3; kh++) {
            const unsigned char* Akh = Ab + kh * A_STRIDE;
            const unsigned char* Bkh = Bb + kh * 128;   // k += 64 -> 128 bytes
            #pragma unroll
            for (int kk = 0; kk < 4; kk++) {
                u32 a[4][4], bf[8][2];
                #pragma unroll
                for (int mt = 0; mt < 4; mt++) {
                    const unsigned char* p = Akh + mt * (16 * A_STRIDE) + kk * 32;
                    a[mt][0] = *(const u32*)p;
                    a[mt][1] = *(const u32*)(p + 8 * A_STRIDE);
                    a[mt][2] = *(const u32*)(p + 16);
                    a[mt][3] = *(const u32*)(p + 8 * A_STRIDE + 16);
                }
                #pragma unroll
                for (int nt = 0; nt < 8; nt++) {
                    const unsigned char* q = Bkh + nt * (8 * B_STRIDE) + kk * 32;
                    bf[nt][0] = *(const u32*)q;
                    bf[nt][1] = *(const u32*)(q + 16);
                }
                #pragma unroll
                for (int mt = 0; mt < 4; mt++)
                    #pragma unroll
                    for (int nt = 0; nt < 8; nt++)
                        mma16816(C[mt][nt], a[mt], bf[nt]);
            }
        }
    }

    // ---- epilogue: bias + x-tap + LSTM elementwise ----
    const float* xs  = (const float*)(sm + OFF_X);
    const float* wxs = (const float*)(sm + OFF_WX);
    const float* bss = (const float*)(sm + OFF_BIAS);

    #pragma unroll
    for (int mt = 0; mt < 4; mt++) {
        #pragma unroll
        for (int rh = 0; rh < 2; rh++) {
            const int prow = wm * 64 + mt * 16 + g + rh * 8;
            const int pos  = p0 + prow;
            const float xm1 = xs[prow], x0 = xs[prow + 1], xp1 = xs[prow + 2];
            #pragma unroll
            for (int bl = 0; bl < 2; bl++) {
                const int chl = (2 * wn + bl) * 8 + 2 * tq;
                const size_t base = ((size_t)b * NNPOS + pos) * 64 + hs * 32 + chl;
                float2 cold = *(const float2*)(g_c + base);
                float cc[2], hh[2];
                #pragma unroll
                for (int lsb = 0; lsb < 2; lsb++) {
                    const int nb = wn * 64 + bl * 32 + 2 * tq + lsb;
                    float vi = C[mt][bl * 4 + 0][rh * 2 + lsb] + bss[nb]      + wxs[nb * 3]        * xm1 + wxs[nb * 3 + 1]        * x0 + wxs[nb * 3 + 2]        * xp1;
                    float vf = C[mt][bl * 4 + 1][rh * 2 + lsb] + bss[nb + 8]  + wxs[(nb + 8) * 3]  * xm1 + wxs[(nb + 8) * 3 + 1]  * x0 + wxs[(nb + 8) * 3 + 2]  * xp1;
                    float vo = C[mt][bl * 4 + 2][rh * 2 + lsb] + bss[nb + 16] + wxs[(nb + 16) * 3] * xm1 + wxs[(nb + 16) * 3 + 1] * x0 + wxs[(nb + 16) * 3 + 2] * xp1;
                    float vg = C[mt][bl * 4 + 3][rh * 2 + lsb] + bss[nb + 24] + wxs[(nb + 24) * 3] * xm1 + wxs[(nb + 24) * 3 + 1] * x0 + wxs[(nb + 24) * 3 + 2] * xp1;
                    float co = lsb ? cold.y : cold.x;
                    float c2 = sigm(vf) * co + sigm(vi) * tanhq(vg);
                    cc[lsb] = c2;
                    hh[lsb] = sigm(vo) * tanhq(c2);
                }
                *(float2*)(g_c + base) = make_float2(cc[0], cc[1]);
                __nv_bfloat162 vhi, vlo;
                vhi.x = __float2bfloat16(hh[0]);
                vhi.y = __float2bfloat16(hh[1]);
                vlo.x = __float2bfloat16(hh[0] - __bfloat162float(vhi.x));
                vlo.y = __float2bfloat16(hh[1] - __bfloat162float(vhi.y));
                *(__nv_bfloat162*)&g_hp[wr][0][base] = vhi;
                *(__nv_bfloat162*)&g_hp[wr][1][base] = vlo;
            }
        }
    }
}

// ---- final 1x1 conv + broadcast over TS (final h in buf 0) ----
__global__ void __launch_bounds__(256)
fc_kernel(const float* __restrict__ fc_w, const float* __restrict__ fc_b,
          float* __restrict__ out) {
    __shared__ float w_s[HIDDEN];
    int tid = threadIdx.x;
    if (tid < HIDDEN) w_s[tid] = fc_w[tid];
    __syncthreads();

    int b = blockIdx.y;
    int n = blockIdx.x * 256 + tid;
    const __nv_bfloat16* hhi = &g_hp[0][0][((size_t)b * NNPOS + n) * 64];
    const __nv_bfloat16* hlo = &g_hp[0][1][((size_t)b * NNPOS + n) * 64];
    float acc = fc_b[0];
    #pragma unroll
    for (int ch = 0; ch < HIDDEN; ch++)
        acc += (__bfloat162float(hhi[ch]) + __bfloat162float(hlo[ch])) * w_s[ch];

    #pragma unroll
    for (int t = 0; t < TSTEPS; t++)
        out[((size_t)b * TSTEPS + t) * NNPOS + n] = acc;
}

extern "C" void kernel_launch(void* const* d_in, const int* in_sizes, int n_in,
                              void* d_out, int out_size) {
    const float* x      = (const float*)d_in[0];  // [16,16,4096,1]
    const float* conv_w = (const float*)d_in[1];  // [256,65,3,3]
    const float* conv_b = (const float*)d_in[2];  // [256]
    const float* fc_w   = (const float*)d_in[3];  // [1,64,1,1]
    const float* fc_b   = (const float*)d_in[4];  // [1]
    float* out = (float*)d_out;                   // [16,16,4096,1]

    cudaFuncSetAttribute(lstm_step, cudaFuncAttributeMaxDynamicSharedMemorySize, SMEM_BYTES);

    repack_img<<<(2 * 128 * 192 + 255) / 256, 256>>>(conv_w);
    zero_state<<<1024, 256>>>();

    for (int t = 0; t < TSTEPS; t++)
        lstm_step<<<dim3(NNPOS / TILE_P, 2, BATCH), 256, SMEM_BYTES>>>(x, conv_w, conv_b, t);

    fc_kernel<<<dim3(NNPOS / 256, BATCH), 256>>>(fc_w, fc_b, out);
}

// round 8
// speedup vs baseline: 2.3875x; 1.2253x over previous
#include <cuda_runtime.h>
#include <cuda_bf16.h>
#include <math.h>

#define HIDDEN 64
#define BATCH  16
#define TSTEPS 16
#define NNPOS  4096
#define TILE_P 256
#define NTHREADS 512

typedef unsigned int u32;

// ---- smem layout (bytes) ----
#define A_STRIDE 144            // 64 bf16 = 128B padded to 144 (conflict-free frags)
#define B_STRIDE 400            // 192 bf16 = 384B padded to 400
#define APLANE   (258 * A_STRIDE)          // 37152
#define BPLANE   (128 * B_STRIDE)          // 51200
#define OFF_A    0                          // 2 planes: hi, lo
#define OFF_B    (2 * APLANE)               // 74304; 2 planes
#define OFF_X    (OFF_B + 2 * BPLANE)       // 176704; 258 floats
#define OFF_WX   (OFF_X + 258 * 4)          // 177736; 128*3 floats
#define OFF_BIAS (OFF_WX + 128 * 3 * 4)     // 179272; 128 floats
#define SMEM_BYTES (OFF_BIAS + 512)         // 179784

// ---- persistent scratch ----
// weight image: [hs][plane][n][192] bf16, n-row: gate=(n>>3)&3, chl=(n>>5)*8+(n&7)
__device__ __align__(16) __nv_bfloat16 g_wimg[2 * 2 * 128 * 192];
__device__ __align__(16) __nv_bfloat16 g_hp[2][2][(size_t)BATCH * NNPOS * HIDDEN]; // [buf][plane][(b*NN+p)*64+ch]
__device__ __align__(16) float         g_c[(size_t)BATCH * NNPOS * HIDDEN];

__device__ __forceinline__ float sigm(float v)  { return 1.f / (1.f + __expf(-v)); }
__device__ __forceinline__ float tanhq(float v) { return 1.f - 2.f / (__expf(2.f * v) + 1.f); }

__device__ __forceinline__ void mma16816(float* c, const u32* a, const u32* bf) {
    asm volatile(
        "mma.sync.aligned.m16n8k16.row.col.f32.bf16.bf16.f32 "
        "{%0,%1,%2,%3},{%4,%5,%6,%7},{%8,%9},{%0,%1,%2,%3};"
        : "+f"(c[0]), "+f"(c[1]), "+f"(c[2]), "+f"(c[3])
        : "r"(a[0]), "r"(a[1]), "r"(a[2]), "r"(a[3]), "r"(bf[0]), "r"(bf[1]));
}

// ---- setup: weight image ----
__global__ void repack_img(const float* __restrict__ conv_w) {
    int idx = blockIdx.x * blockDim.x + threadIdx.x;
    if (idx >= 2 * 128 * 192) return;
    int hs  = idx / 24576;
    int rem = idx % 24576;
    int n = rem / 192, k = rem % 192;
    int gate = (n >> 3) & 3;
    int chl  = (n >> 5) * 8 + (n & 7);
    int oc = gate * 64 + hs * 32 + chl;
    int kh = k / 64, ic = k % 64;
    float w = conv_w[((oc * 65 + (ic + 1)) * 3 + kh) * 3 + 1];
    __nv_bfloat16 whi = __float2bfloat16(w);
    __nv_bfloat16 wlo = __float2bfloat16(w - __bfloat162float(whi));
    g_wimg[((size_t)(hs * 2 + 0) * 128 + n) * 192 + k] = whi;
    g_wimg[((size_t)(hs * 2 + 1) * 128 + n) * 192 + k] = wlo;
}

__global__ void zero_state() {
    size_t i = (size_t)blockIdx.x * blockDim.x + threadIdx.x;
    size_t stride = (size_t)gridDim.x * blockDim.x;
    const size_t nc = (size_t)BATCH * NNPOS * HIDDEN;
    for (size_t j = i; j < nc; j += stride) g_c[j] = 0.f;
    u32* h0 = (u32*)&g_hp[0][0][0];            // both planes of buf0 contiguous
    for (size_t j = i; j < nc; j += stride) h0[j] = 0u;
}

// ---- one timestep: 512 threads, 16 warps, warp tile 64x32 ----
__global__ void __launch_bounds__(NTHREADS, 1)
lstm_step(const float* __restrict__ x, const float* __restrict__ conv_w,
          const float* __restrict__ conv_b, int t) {
    extern __shared__ unsigned char sm[];
    const int tid = threadIdx.x, wid = tid >> 5, lane = tid & 31;
    const int g = lane >> 2, tq = lane & 3;
    const int p0 = blockIdx.x * TILE_P;
    const int hs = blockIdx.y;
    const int b  = blockIdx.z;
    const int rd = t & 1, wr = rd ^ 1;

    // ---- stage B: 2 planes x 128 rows x 24 uint4 ----
    {
        const uint4* src = (const uint4*)(g_wimg + (size_t)hs * 2 * 128 * 192);
        #pragma unroll
        for (int m = tid; m < 2 * 128 * 24; m += NTHREADS) {
            int pl = m / 3072, r = (m % 3072) / 24, c = m % 24;
            *(uint4*)(sm + OFF_B + pl * BPLANE + r * B_STRIDE + c * 16) = src[m];
        }
    }
    // ---- stage A (h rows p0-1..p0+256): 2 planes x 258 rows x 8 uint4 ----
    {
        const uint4 z4 = make_uint4(0, 0, 0, 0);
        #pragma unroll
        for (int m = tid; m < 2 * 258 * 8; m += NTHREADS) {
            int pl = m / 2064, r = (m % 2064) / 8, c = m % 8;
            int pos = p0 - 1 + r;
            uint4 v = z4;
            if (pos >= 0 && pos < NNPOS)
                v = ((const uint4*)&g_hp[rd][pl][((size_t)b * NNPOS + pos) * 64])[c];
            *(uint4*)(sm + OFF_A + pl * APLANE + r * A_STRIDE + c * 16) = v;
        }
    }
    // ---- stage x, wx, bias ----
    if (tid < 258) {
        int pos = p0 - 1 + tid;
        ((float*)(sm + OFF_X))[tid] =
            (pos >= 0 && pos < NNPOS) ? x[((size_t)b * TSTEPS + t) * NNPOS + pos] : 0.f;
    }
    if (tid >= 384 && tid < 512) {
        int n = tid - 384;
        int gate = (n >> 3) & 3;
        int chl  = (n >> 5) * 8 + (n & 7);
        int oc = gate * 64 + hs * 32 + chl;
        ((float*)(sm + OFF_BIAS))[n] = conv_b[oc];
        #pragma unroll
        for (int kh = 0; kh < 3; kh++)
            ((float*)(sm + OFF_WX))[n * 3 + kh] = conv_w[((oc * 65 + 0) * 3 + kh) * 3 + 1];
    }
    __syncthreads();

    // ---- mainloop: 16 warps, warp tile 64x32 (wm 0..3, wn 0..3) ----
    const int wm = wid >> 2, wn = wid & 3;
    float C[4][4][4];
    #pragma unroll
    for (int mt = 0; mt < 4; mt++)
        #pragma unroll
        for (int nt = 0; nt < 4; nt++)
            #pragma unroll
            for (int r = 0; r < 4; r++) C[mt][nt][r] = 0.f;

    const unsigned char* Arow = sm + OFF_A + (wm * 64 + g) * A_STRIDE + tq * 4;
    const unsigned char* Brow = sm + OFF_B + (wn * 32 + g) * B_STRIDE + tq * 4;

    #pragma unroll 1
    for (int pass = 0; pass < 3; pass++) {
        const unsigned char* Ab = Arow + (pass == 1 ? APLANE : 0);
        const unsigned char* Bb = Brow + (pass == 2 ? BPLANE : 0);
        #pragma unroll 1
        for (int kh = 0; kh < 3; kh++) {
            const unsigned char* Akh = Ab + kh * A_STRIDE;
            const unsigned char* Bkh = Bb + kh * 128;   // k += 64 -> 128 bytes
            #pragma unroll
            for (int kk = 0; kk < 4; kk++) {
                u32 a[4][4], bf[4][2];
                #pragma unroll
                for (int mt = 0; mt < 4; mt++) {
                    const unsigned char* p = Akh + mt * (16 * A_STRIDE) + kk * 32;
                    a[mt][0] = *(const u32*)p;
                    a[mt][1] = *(const u32*)(p + 8 * A_STRIDE);
                    a[mt][2] = *(const u32*)(p + 16);
                    a[mt][3] = *(const u32*)(p + 8 * A_STRIDE + 16);
                }
                #pragma unroll
                for (int nt = 0; nt < 4; nt++) {
                    const unsigned char* q = Bkh + nt * (8 * B_STRIDE) + kk * 32;
                    bf[nt][0] = *(const u32*)q;
                    bf[nt][1] = *(const u32*)(q + 16);
                }
                #pragma unroll
                for (int mt = 0; mt < 4; mt++)
                    #pragma unroll
                    for (int nt = 0; nt < 4; nt++)
                        mma16816(C[mt][nt], a[mt], bf[nt]);
            }
        }
    }

    // ---- epilogue: nt == gate (n = wn*32 + gate*8 + 2tq + lsb) ----
    const float* xs  = (const float*)(sm + OFF_X);
    const float* wxs = (const float*)(sm + OFF_WX);
    const float* bss = (const float*)(sm + OFF_BIAS);

    #pragma unroll
    for (int mt = 0; mt < 4; mt++) {
        #pragma unroll
        for (int rh = 0; rh < 2; rh++) {
            const int prow = wm * 64 + mt * 16 + g + rh * 8;
            const int pos  = p0 + prow;
            const float xm1 = xs[prow], x0 = xs[prow + 1], xp1 = xs[prow + 2];
            const int chl = wn * 8 + 2 * tq;
            const size_t base = ((size_t)b * NNPOS + pos) * 64 + hs * 32 + chl;
            float2 cold = *(const float2*)(g_c + base);
            float cc[2], hh[2];
            #pragma unroll
            for (int lsb = 0; lsb < 2; lsb++) {
                const int nb = wn * 32 + 2 * tq + lsb;   // + gate*8 below
                float vi = C[mt][0][rh * 2 + lsb] + bss[nb]      + wxs[nb * 3]        * xm1 + wxs[nb * 3 + 1]        * x0 + wxs[nb * 3 + 2]        * xp1;
                float vf = C[mt][1][rh * 2 + lsb] + bss[nb + 8]  + wxs[(nb + 8) * 3]  * xm1 + wxs[(nb + 8) * 3 + 1]  * x0 + wxs[(nb + 8) * 3 + 2]  * xp1;
                float vo = C[mt][2][rh * 2 + lsb] + bss[nb + 16] + wxs[(nb + 16) * 3] * xm1 + wxs[(nb + 16) * 3 + 1] * x0 + wxs[(nb + 16) * 3 + 2] * xp1;
                float vg = C[mt][3][rh * 2 + lsb] + bss[nb + 24] + wxs[(nb + 24) * 3] * xm1 + wxs[(nb + 24) * 3 + 1] * x0 + wxs[(nb + 24) * 3 + 2] * xp1;
                float co = lsb ? cold.y : cold.x;
                float c2 = sigm(vf) * co + sigm(vi) * tanhq(vg);
                cc[lsb] = c2;
                hh[lsb] = sigm(vo) * tanhq(c2);
            }
            *(float2*)(g_c + base) = make_float2(cc[0], cc[1]);
            __nv_bfloat162 vhi, vlo;
            vhi.x = __float2bfloat16(hh[0]);
            vhi.y = __float2bfloat16(hh[1]);
            vlo.x = __float2bfloat16(hh[0] - __bfloat162float(vhi.x));
            vlo.y = __float2bfloat16(hh[1] - __bfloat162float(vhi.y));
            *(__nv_bfloat162*)&g_hp[wr][0][base] = vhi;
            *(__nv_bfloat162*)&g_hp[wr][1][base] = vlo;
        }
    }
}

// ---- final 1x1 conv + broadcast over TS (final h in buf 0) ----
__global__ void __launch_bounds__(256)
fc_kernel(const float* __restrict__ fc_w, const float* __restrict__ fc_b,
          float* __restrict__ out) {
    __shared__ float w_s[HIDDEN];
    int tid = threadIdx.x;
    if (tid < HIDDEN) w_s[tid] = fc_w[tid];
    __syncthreads();

    int b = blockIdx.y;
    int n = blockIdx.x * 256 + tid;
    const __nv_bfloat16* hhi = &g_hp[0][0][((size_t)b * NNPOS + n) * 64];
    const __nv_bfloat16* hlo = &g_hp[0][1][((size_t)b * NNPOS + n) * 64];
    float acc = fc_b[0];
    #pragma unroll
    for (int ch = 0; ch < HIDDEN; ch++)
        acc += (__bfloat162float(hhi[ch]) + __bfloat162float(hlo[ch])) * w_s[ch];

    #pragma unroll
    for (int t = 0; t < TSTEPS; t++)
        out[((size_t)b * TSTEPS + t) * NNPOS + n] = acc;
}

extern "C" void kernel_launch(void* const* d_in, const int* in_sizes, int n_in,
                              void* d_out, int out_size) {
    const float* x      = (const float*)d_in[0];  // [16,16,4096,1]
    const float* conv_w = (const float*)d_in[1];  // [256,65,3,3]
    const float* conv_b = (const float*)d_in[2];  // [256]
    const float* fc_w   = (const float*)d_in[3];  // [1,64,1,1]
    const float* fc_b   = (const float*)d_in[4];  // [1]
    float* out = (float*)d_out;                   // [16,16,4096,1]

    cudaFuncSetAttribute(lstm_step, cudaFuncAttributeMaxDynamicSharedMemorySize, SMEM_BYTES);

    repack_img<<<(2 * 128 * 192 + 255) / 256, 256>>>(conv_w);
    zero_state<<<1024, 256>>>();

    for (int t = 0; t < TSTEPS; t++)
        lstm_step<<<dim3(NNPOS / TILE_P, 2, BATCH), NTHREADS, SMEM_BYTES>>>(x, conv_w, conv_b, t);

    fc_kernel<<<dim3(NNPOS / 256, BATCH), 256>>>(fc_w, fc_b, out);
}

// round 9
// speedup vs baseline: 2.4229x; 1.0148x over previous
#include <cuda_runtime.h>
#include <cuda_bf16.h>
#include <math.h>

#define HIDDEN 64
#define BATCH  16
#define TSTEPS 16
#define NNPOS  4096
#define TILE_P 256
#define NTHREADS 512

typedef unsigned int u32;

// ---- smem layout (bytes) ----
#define A_STRIDE 144            // 64 bf16 = 128B padded to 144 (conflict-free frags)
#define B_STRIDE 400            // 192 bf16 = 384B padded to 400
#define APLANE   (258 * A_STRIDE)          // 37152
#define BPLANE   (128 * B_STRIDE)          // 51200
#define OFF_A    0                          // 2 planes: hi, lo
#define OFF_B    (2 * APLANE)               // 74304; 2 planes
#define OFF_X    (OFF_B + 2 * BPLANE)       // 176704; 258 floats
#define OFF_WX   (OFF_X + 258 * 4)          // 177736; 128*3 floats
#define OFF_BIAS (OFF_WX + 128 * 3 * 4)     // 179272; 128 floats
#define SMEM_BYTES (OFF_BIAS + 512)         // 179784

// ---- persistent scratch ----
// weight image: [hs][plane][n][192] bf16, n-row: gate=(n>>3)&3, chl=(n>>5)*8+(n&7)
__device__ __align__(16) __nv_bfloat16 g_wimg[2 * 2 * 128 * 192];
__device__ __align__(16) __nv_bfloat16 g_hp[2][2][(size_t)BATCH * NNPOS * HIDDEN]; // [buf][plane][(b*NN+p)*64+ch]
__device__ __align__(16) float         g_c[(size_t)BATCH * NNPOS * HIDDEN];

__device__ __forceinline__ float sigm(float v)  { return 1.f / (1.f + __expf(-v)); }
__device__ __forceinline__ float tanhq(float v) { return 1.f - 2.f / (__expf(2.f * v) + 1.f); }

__device__ __forceinline__ void mma16816(float* c, const u32* a, const u32* bf) {
    asm volatile(
        "mma.sync.aligned.m16n8k16.row.col.f32.bf16.bf16.f32 "
        "{%0,%1,%2,%3},{%4,%5,%6,%7},{%8,%9},{%0,%1,%2,%3};"
        : "+f"(c[0]), "+f"(c[1]), "+f"(c[2]), "+f"(c[3])
        : "r"(a[0]), "r"(a[1]), "r"(a[2]), "r"(a[3]), "r"(bf[0]), "r"(bf[1]));
}

// ---- setup: weight image ----
__global__ void repack_img(const float* __restrict__ conv_w) {
    int idx = blockIdx.x * blockDim.x + threadIdx.x;
    if (idx >= 2 * 128 * 192) return;
    int hs  = idx / 24576;
    int rem = idx % 24576;
    int n = rem / 192, k = rem % 192;
    int gate = (n >> 3) & 3;
    int chl  = (n >> 5) * 8 + (n & 7);
    int oc = gate * 64 + hs * 32 + chl;
    int kh = k / 64, ic = k % 64;
    float w = conv_w[((oc * 65 + (ic + 1)) * 3 + kh) * 3 + 1];
    __nv_bfloat16 whi = __float2bfloat16(w);
    __nv_bfloat16 wlo = __float2bfloat16(w - __bfloat162float(whi));
    g_wimg[((size_t)(hs * 2 + 0) * 128 + n) * 192 + k] = whi;
    g_wimg[((size_t)(hs * 2 + 1) * 128 + n) * 192 + k] = wlo;
}

__global__ void zero_state() {
    size_t i = (size_t)blockIdx.x * blockDim.x + threadIdx.x;
    size_t stride = (size_t)gridDim.x * blockDim.x;
    const size_t nc = (size_t)BATCH * NNPOS * HIDDEN;
    for (size_t j = i; j < nc; j += stride) g_c[j] = 0.f;
    u32* h0 = (u32*)&g_hp[0][0][0];            // both planes of buf0 contiguous
    for (size_t j = i; j < nc; j += stride) h0[j] = 0u;
}

// ---- one timestep: 512 threads, 16 warps, warp tile 64x32, fused 3-stream ----
__global__ void __launch_bounds__(NTHREADS, 1)
lstm_step(const float* __restrict__ x, const float* __restrict__ conv_w,
          const float* __restrict__ conv_b, int t) {
    extern __shared__ unsigned char sm[];
    const int tid = threadIdx.x, wid = tid >> 5, lane = tid & 31;
    const int g = lane >> 2, tq = lane & 3;
    const int p0 = blockIdx.x * TILE_P;
    const int hs = blockIdx.y;
    const int b  = blockIdx.z;
    const int rd = t & 1, wr = rd ^ 1;

    // ---- stage B: 2 planes x 128 rows x 24 uint4 ----
    {
        const uint4* src = (const uint4*)(g_wimg + (size_t)hs * 2 * 128 * 192);
        #pragma unroll
        for (int m = tid; m < 2 * 128 * 24; m += NTHREADS) {
            int pl = m / 3072, r = (m % 3072) / 24, c = m % 24;
            *(uint4*)(sm + OFF_B + pl * BPLANE + r * B_STRIDE + c * 16) = src[m];
        }
    }
    // ---- stage A (h rows p0-1..p0+256): 2 planes x 258 rows x 8 uint4 ----
    {
        const uint4 z4 = make_uint4(0, 0, 0, 0);
        #pragma unroll
        for (int m = tid; m < 2 * 258 * 8; m += NTHREADS) {
            int pl = m / 2064, r = (m % 2064) / 8, c = m % 8;
            int pos = p0 - 1 + r;
            uint4 v = z4;
            if (pos >= 0 && pos < NNPOS)
                v = ((const uint4*)&g_hp[rd][pl][((size_t)b * NNPOS + pos) * 64])[c];
            *(uint4*)(sm + OFF_A + pl * APLANE + r * A_STRIDE + c * 16) = v;
        }
    }
    // ---- stage x, wx, bias ----
    if (tid < 258) {
        int pos = p0 - 1 + tid;
        ((float*)(sm + OFF_X))[tid] =
            (pos >= 0 && pos < NNPOS) ? x[((size_t)b * TSTEPS + t) * NNPOS + pos] : 0.f;
    }
    if (tid >= 384 && tid < 512) {
        int n = tid - 384;
        int gate = (n >> 3) & 3;
        int chl  = (n >> 5) * 8 + (n & 7);
        int oc = gate * 64 + hs * 32 + chl;
        ((float*)(sm + OFF_BIAS))[n] = conv_b[oc];
        #pragma unroll
        for (int kh = 0; kh < 3; kh++)
            ((float*)(sm + OFF_WX))[n * 3 + kh] = conv_w[((oc * 65 + 0) * 3 + kh) * 3 + 1];
    }
    __syncthreads();

    // ---- mainloop: 16 warps, warp tile 64x32; fused hi*hi + lo*hi + hi*lo ----
    const int wm = wid >> 2, wn = wid & 3;
    float C[4][4][4];
    #pragma unroll
    for (int mt = 0; mt < 4; mt++)
        #pragma unroll
        for (int nt = 0; nt < 4; nt++)
            #pragma unroll
            for (int r = 0; r < 4; r++) C[mt][nt][r] = 0.f;

    const unsigned char* Arow = sm + OFF_A + (wm * 64 + g) * A_STRIDE + tq * 4;
    const unsigned char* Brow = sm + OFF_B + (wn * 32 + g) * B_STRIDE + tq * 4;

    #pragma unroll 1
    for (int kh = 0; kh < 3; kh++) {
        const unsigned char* Akh = Arow + kh * A_STRIDE;
        const unsigned char* Bkh = Brow + kh * 128;      // k += 64 -> 128 bytes
        #pragma unroll
        for (int kk = 0; kk < 4; kk++) {
            // B fragments for this kk: hi and lo planes
            u32 bh[4][2], bl[4][2];
            #pragma unroll
            for (int nt = 0; nt < 4; nt++) {
                const unsigned char* q = Bkh + nt * (8 * B_STRIDE) + kk * 32;
                bh[nt][0] = *(const u32*)q;
                bh[nt][1] = *(const u32*)(q + 16);
                bl[nt][0] = *(const u32*)(q + BPLANE);
                bl[nt][1] = *(const u32*)(q + BPLANE + 16);
            }
            #pragma unroll
            for (int mt = 0; mt < 4; mt++) {
                const unsigned char* p = Akh + mt * (16 * A_STRIDE) + kk * 32;
                u32 ah[4], al[4];
                ah[0] = *(const u32*)p;
                ah[1] = *(const u32*)(p + 8 * A_STRIDE);
                ah[2] = *(const u32*)(p + 16);
                ah[3] = *(const u32*)(p + 8 * A_STRIDE + 16);
                al[0] = *(const u32*)(p + APLANE);
                al[1] = *(const u32*)(p + APLANE + 8 * A_STRIDE);
                al[2] = *(const u32*)(p + APLANE + 16);
                al[3] = *(const u32*)(p + APLANE + 8 * A_STRIDE + 16);
                #pragma unroll
                for (int nt = 0; nt < 4; nt++) {
                    mma16816(C[mt][nt], ah, bh[nt]);   // hi*hi
                    mma16816(C[mt][nt], al, bh[nt]);   // lo*hi
                    mma16816(C[mt][nt], ah, bl[nt]);   // hi*lo
                }
            }
        }
    }

    // ---- epilogue: nt == gate (n = wn*32 + gate*8 + 2tq + lsb) ----
    const float* xs  = (const float*)(sm + OFF_X);
    const float* wxs = (const float*)(sm + OFF_WX);
    const float* bss = (const float*)(sm + OFF_BIAS);

    #pragma unroll
    for (int mt = 0; mt < 4; mt++) {
        #pragma unroll
        for (int rh = 0; rh < 2; rh++) {
            const int prow = wm * 64 + mt * 16 + g + rh * 8;
            const int pos  = p0 + prow;
            const float xm1 = xs[prow], x0 = xs[prow + 1], xp1 = xs[prow + 2];
            const int chl = wn * 8 + 2 * tq;
            const size_t base = ((size_t)b * NNPOS + pos) * 64 + hs * 32 + chl;
            float2 cold = *(const float2*)(g_c + base);
            float cc[2], hh[2];
            #pragma unroll
            for (int lsb = 0; lsb < 2; lsb++) {
                const int nb = wn * 32 + 2 * tq + lsb;
                float vi = C[mt][0][rh * 2 + lsb] + bss[nb]      + wxs[nb * 3]        * xm1 + wxs[nb * 3 + 1]        * x0 + wxs[nb * 3 + 2]        * xp1;
                float vf = C[mt][1][rh * 2 + lsb] + bss[nb + 8]  + wxs[(nb + 8) * 3]  * xm1 + wxs[(nb + 8) * 3 + 1]  * x0 + wxs[(nb + 8) * 3 + 2]  * xp1;
                float vo = C[mt][2][rh * 2 + lsb] + bss[nb + 16] + wxs[(nb + 16) * 3] * xm1 + wxs[(nb + 16) * 3 + 1] * x0 + wxs[(nb + 16) * 3 + 2] * xp1;
                float vg = C[mt][3][rh * 2 + lsb] + bss[nb + 24] + wxs[(nb + 24) * 3] * xm1 + wxs[(nb + 24) * 3 + 1] * x0 + wxs[(nb + 24) * 3 + 2] * xp1;
                float co = lsb ? cold.y : cold.x;
                float c2 = sigm(vf) * co + sigm(vi) * tanhq(vg);
                cc[lsb] = c2;
                hh[lsb] = sigm(vo) * tanhq(c2);
            }
            *(float2*)(g_c + base) = make_float2(cc[0], cc[1]);
            __nv_bfloat162 vhi, vlo;
            vhi.x = __float2bfloat16(hh[0]);
            vhi.y = __float2bfloat16(hh[1]);
            vlo.x = __float2bfloat16(hh[0] - __bfloat162float(vhi.x));
            vlo.y = __float2bfloat16(hh[1] - __bfloat162float(vhi.y));
            *(__nv_bfloat162*)&g_hp[wr][0][base] = vhi;
            *(__nv_bfloat162*)&g_hp[wr][1][base] = vlo;
        }
    }
}

// ---- final 1x1 conv + broadcast over TS (final h in buf 0) ----
__global__ void __launch_bounds__(256)
fc_kernel(const float* __restrict__ fc_w, const float* __restrict__ fc_b,
          float* __restrict__ out) {
    __shared__ float w_s[HIDDEN];
    int tid = threadIdx.x;
    if (tid < HIDDEN) w_s[tid] = fc_w[tid];
    __syncthreads();

    int b = blockIdx.y;
    int n = blockIdx.x * 256 + tid;
    const __nv_bfloat16* hhi = &g_hp[0][0][((size_t)b * NNPOS + n) * 64];
    const __nv_bfloat16* hlo = &g_hp[0][1][((size_t)b * NNPOS + n) * 64];
    float acc = fc_b[0];
    #pragma unroll
    for (int ch = 0; ch < HIDDEN; ch++)
        acc += (__bfloat162float(hhi[ch]) + __bfloat162float(hlo[ch])) * w_s[ch];

    #pragma unroll
    for (int t = 0; t < TSTEPS; t++)
        out[((size_t)b * TSTEPS + t) * NNPOS + n] = acc;
}

extern "C" void kernel_launch(void* const* d_in, const int* in_sizes, int n_in,
                              void* d_out, int out_size) {
    const float* x      = (const float*)d_in[0];  // [16,16,4096,1]
    const float* conv_w = (const float*)d_in[1];  // [256,65,3,3]
    const float* conv_b = (const float*)d_in[2];  // [256]
    const float* fc_w   = (const float*)d_in[3];  // [1,64,1,1]
    const float* fc_b   = (const float*)d_in[4];  // [1]
    float* out = (float*)d_out;                   // [16,16,4096,1]

    cudaFuncSetAttribute(lstm_step, cudaFuncAttributeMaxDynamicSharedMemorySize, SMEM_BYTES);

    repack_img<<<(2 * 128 * 192 + 255) / 256, 256>>>(conv_w);
    zero_state<<<1024, 256>>>();

    for (int t = 0; t < TSTEPS; t++)
        lstm_step<<<dim3(NNPOS / TILE_P, 2, BATCH), NTHREADS, SMEM_BYTES>>>(x, conv_w, conv_b, t);

    fc_kernel<<<dim3(NNPOS / 256, BATCH), 256>>>(fc_w, fc_b, out);
}